// round 12
// baseline (speedup 1.0000x reference)
#include <cuda_runtime.h>
#include <cuda_fp16.h>
#include <stdint.h>
#include <math.h>

// ---------------- problem constants ----------------
constexpr int NV   = 16384;
constexpr int EDG  = 131072;
constexpr int ETOT = EDG + NV;
constexpr int HC   = 512;
constexpr int CC   = 128;
constexpr int D1   = 513;
constexpr int BB   = 128;
constexpr int DA   = 2049;

// ---------------- device scratch ----------------
__device__ float g_xl[NV * HC];
__device__ float g_xr[NV * HC];
__device__ float g_h3[NV * D1];
__device__ int   g_deg[NV];          // zero-initialized; re-zeroed by scan each run
__device__ int   g_off[NV + 1];
__device__ int   g_cur[NV];
__device__ int   g_srcv[ETOT];
__device__ float g_za[BB * DA];
__device__ float g_z2[BB * DA];
__device__ float g_zb[BB * D1];
__device__ float g_z3[BB * D1];
__device__ float g_zf[BB * D1];
__device__ __half g_A16[NV * HC];
__device__ __half g_W1t[HC * HC];
__device__ __half g_W2t[HC * HC];
__device__ __half g_W3t[HC * HC];    // layer-2 Wl^T
__device__ __half g_W4t[HC * HC];    // layer-2 Wr^T

// ---------------- helpers ----------------
__device__ __forceinline__ void ldmat_x4(unsigned (&r)[4], unsigned addr) {
    asm volatile("ldmatrix.sync.aligned.m8n8.x4.shared.b16 {%0,%1,%2,%3}, [%4];"
        : "=r"(r[0]), "=r"(r[1]), "=r"(r[2]), "=r"(r[3]) : "r"(addr));
}
__device__ __forceinline__ void ldmat_x2(unsigned (&r)[2], unsigned addr) {
    asm volatile("ldmatrix.sync.aligned.m8n8.x2.shared.b16 {%0,%1}, [%2];"
        : "=r"(r[0]), "=r"(r[1]) : "r"(addr));
}
__device__ __forceinline__ void mma16816h(float (&d)[4], const unsigned (&a)[4], const unsigned (&b)[2]) {
    asm volatile("mma.sync.aligned.m16n8k16.row.col.f32.f16.f16.f32 "
        "{%0,%1,%2,%3},{%4,%5,%6,%7},{%8,%9},{%0,%1,%2,%3};"
        : "+f"(d[0]), "+f"(d[1]), "+f"(d[2]), "+f"(d[3])
        : "r"(a[0]), "r"(a[1]), "r"(a[2]), "r"(a[3]), "r"(b[0]), "r"(b[1]));
}
__device__ __forceinline__ unsigned smem_u32(const void* p) {
    return (unsigned)__cvta_generic_to_shared(p);
}
__device__ __forceinline__ void cp16(unsigned saddr, const void* g) {
    asm volatile("cp.async.cg.shared.global [%0], [%1], 16;" :: "r"(saddr), "l"(g));
}

// ---------------- shared bodies ----------------
__device__ __forceinline__ void convA_body(int i, const float* __restrict__ A, int lda,
                                           __half* __restrict__ Ah) {
    int row = i >> 7, c4 = (i & 127) * 4;
    const float* ap = A + (size_t)row * lda + c4;
    __half2 H0 = {__float2half_rn(ap[0]), __float2half_rn(ap[1])};
    __half2 H1 = {__float2half_rn(ap[2]), __float2half_rn(ap[3])};
    *(uint2*)&Ah[(size_t)row * 512 + c4] = make_uint2(*(unsigned*)&H0, *(unsigned*)&H1);
}

__device__ __forceinline__ void splitWT_body(int tile, int tid,
                                             const float* __restrict__ W,
                                             __half* __restrict__ T,
                                             float (*t)[33]) {
    int bn = (tile & 15) * 32, bk = (tile >> 4) * 32;
    int tx = tid & 31, ty = tid >> 5;
#pragma unroll
    for (int i = 0; i < 4; i++) {
        int k = bk + ty + i * 8;
        t[ty + i * 8][tx] = W[(size_t)k * 512 + bn + tx];
    }
    __syncthreads();
#pragma unroll
    for (int i = 0; i < 4; i++) {
        int n = bn + ty + i * 8;
        T[(size_t)n * 512 + bk + tx] = __float2half_rn(t[tx][ty + i * 8]);
    }
}

// ---------------- L1: fused prep (convA + 4x splitWT + hist) ----------------
__global__ void __launch_bounds__(256) prep_kernel(
    const float* __restrict__ x, const int* __restrict__ ei,
    const float* __restrict__ Wl1, const float* __restrict__ Wr1,
    const float* __restrict__ Wl2, const float* __restrict__ Wr2,
    __half* __restrict__ Ah)
{
    __shared__ float t[32][33];
    int b = blockIdx.x, tid = threadIdx.x;
    if (b < 8192) {
        convA_body(b * 256 + tid, x + 1, D1, Ah);
    } else if (b < 8448) {
        splitWT_body(b - 8192, tid, Wl1, g_W1t, t);
    } else if (b < 8704) {
        splitWT_body(b - 8448, tid, Wr1, g_W2t, t);
    } else if (b < 8960) {
        splitWT_body(b - 8704, tid, Wl2, g_W3t, t);
    } else if (b < 9216) {
        splitWT_body(b - 8960, tid, Wr2, g_W4t, t);
    } else {
        int i = (b - 9216) * 256 + tid;
        if (i < ETOT) {
            int dst = (i < EDG) ? ei[EDG + i] : (i - EDG);
            atomicAdd(&g_deg[dst], 1);
        }
    }
}

// ---------------- L2: scan (also re-zeros g_deg for next run) ----------------
__global__ void scan_kernel() {
    __shared__ int part[1024];
    int t = threadIdx.x;
    int loc[16];
    int s = 0;
#pragma unroll
    for (int i = 0; i < 16; i++) { loc[i] = s; s += g_deg[t * 16 + i]; }
    part[t] = s;
    __syncthreads();
    for (int d = 1; d < 1024; d <<= 1) {
        int v = (t >= d) ? part[t - d] : 0;
        __syncthreads();
        part[t] += v;
        __syncthreads();
    }
    int base = (t > 0) ? part[t - 1] : 0;
#pragma unroll
    for (int i = 0; i < 16; i++) {
        int o = base + loc[i];
        g_off[t * 16 + i] = o;
        g_cur[t * 16 + i] = o;
        g_deg[t * 16 + i] = 0;
    }
    if (t == 1023) g_off[NV] = part[1023];
}

// ---------------- GEMM body (fp16, fp32 accum, BK=64, dual-output) ----------
constexpr int ASTR    = 72;
constexpr int TILE_E  = 128 * ASTR;
constexpr int GEMM_SMEM = 2 * 2 * TILE_E * 2;  // 73728 B

__device__ __forceinline__ void gemm_body(
    int bx, const __half* __restrict__ Ah,
    const __half* __restrict__ W1, const __half* __restrict__ W2,
    const float* __restrict__ b1, const float* __restrict__ b2,
    float* __restrict__ C1, float* __restrict__ C2, __half* smem)
{
    const int tid  = threadIdx.x;
    const int lane = tid & 31;
    const int warp = tid >> 5;
    const int wm   = warp >> 2;
    const int wn   = warp & 3;
    const int bm   = (bx >> 3) * 128;
    const int sub  = bx & 7;
    const bool second = (sub >= 4);
    const int bn   = (sub & 3) * 128;

    const __half* Wt  = second ? W2 : W1;
    const float* bias = second ? b2 : b1;
    float* C          = second ? C2 : C1;

    const __half* gsrc[2] = { Ah + (size_t)bm * 512, Wt + (size_t)bn * 512 };

    float acc[4][4][4];
#pragma unroll
    for (int mt = 0; mt < 4; mt++)
#pragma unroll
        for (int nt = 0; nt < 4; nt++)
#pragma unroll
            for (int q = 0; q < 4; q++) acc[mt][nt][q] = 0.f;

    auto load_tile = [&](int buf, int k0) {
#pragma unroll
        for (int i = 0; i < 8; i++) {
            int id  = tid + i * 256;
            int arr = id >> 10;
            int w   = id & 1023;
            int r   = w >> 3;
            int c16 = w & 7;
            __half* s = smem + (buf * 2 + arr) * TILE_E;
            cp16(smem_u32(s + r * ASTR + c16 * 8),
                 gsrc[arr] + (size_t)r * 512 + k0 + c16 * 8);
        }
        asm volatile("cp.async.commit_group;");
    };

    load_tile(0, 0);

    for (int t = 0; t < 8; t++) {
        int buf = t & 1;
        if (t < 7) load_tile(buf ^ 1, (t + 1) * 64);
        if (t < 7) asm volatile("cp.async.wait_group 1;");
        else       asm volatile("cp.async.wait_group 0;");
        __syncthreads();

        const __half* sA = smem + (buf * 2 + 0) * TILE_E;
        const __half* sB = smem + (buf * 2 + 1) * TILE_E;

#pragma unroll
        for (int ks = 0; ks < 4; ks++) {
            unsigned bf[4][2];
#pragma unroll
            for (int nt = 0; nt < 4; nt++) {
                int n = wn * 32 + nt * 8 + (lane & 7);
                int k = ks * 16 + ((lane >> 3) & 1) * 8;
                ldmat_x2(bf[nt], smem_u32(sB + n * ASTR + k));
            }
#pragma unroll
            for (int mt = 0; mt < 4; mt++) {
                int m = wm * 64 + mt * 16 + ((lane >> 3) & 1) * 8 + (lane & 7);
                int k = ks * 16 + ((lane >> 4) & 1) * 8;
                unsigned af[4];
                ldmat_x4(af, smem_u32(sA + m * ASTR + k));
#pragma unroll
                for (int nt = 0; nt < 4; nt++)
                    mma16816h(acc[mt][nt], af, bf[nt]);
            }
        }
        __syncthreads();
    }

    const int g  = lane >> 2;
    const int t4 = lane & 3;
#pragma unroll
    for (int mt = 0; mt < 4; mt++) {
#pragma unroll
        for (int nt = 0; nt < 4; nt++) {
            int row = bm + wm * 64 + mt * 16 + g;
            int col = bn + wn * 32 + nt * 8 + 2 * t4;
            float2 bv = *(const float2*)&bias[col];
            float2 o0 = make_float2(acc[mt][nt][0] + bv.x, acc[mt][nt][1] + bv.y);
            float2 o1 = make_float2(acc[mt][nt][2] + bv.x, acc[mt][nt][3] + bv.y);
            *(float2*)&C[(size_t)row * 512 + col] = o0;
            *(float2*)&C[(size_t)(row + 8) * 512 + col] = o1;
        }
    }
}

// ---------------- L3: fused scatter + dual GEMM ----------------
__global__ void __launch_bounds__(256, 2) scatter_gemm_kernel(
    const int* __restrict__ ei, const __half* __restrict__ Ah,
    const __half* __restrict__ W1, const __half* __restrict__ W2,
    const float* __restrict__ b1, const float* __restrict__ b2,
    float* __restrict__ C1, float* __restrict__ C2)
{
    extern __shared__ __half smem[];
    if (blockIdx.x < 576) {
        int i = blockIdx.x * 256 + threadIdx.x;
        if (i >= ETOT) return;
        int s, d;
        if (i < EDG) { s = ei[i]; d = ei[EDG + i]; }
        else         { s = d = i - EDG; }
        int p = atomicAdd(&g_cur[d], 1);
        g_srcv[p] = s;
        return;
    }
    gemm_body(blockIdx.x - 576, Ah, W1, W2, b1, b2, C1, C2, smem);
}

// standalone dual GEMM (layer 2)
__global__ void __launch_bounds__(256, 2) gemm_dual_kernel(
    const __half* __restrict__ Ah,
    const __half* __restrict__ W1, const __half* __restrict__ W2,
    const float* __restrict__ b1, const float* __restrict__ b2,
    float* __restrict__ C1, float* __restrict__ C2)
{
    extern __shared__ __half smem[];
    gemm_body(blockIdx.x, Ah, W1, W2, b1, b2, C1, C2, smem);
}

// ---------------- small-M GEMM (MLP tail): 8 rows/thread, 64-thread blocks --
__global__ void __launch_bounds__(64) gemm_small_kernel(
    const float* __restrict__ A, int lda,
    const float* __restrict__ W,
    const float* __restrict__ bias,
    float* __restrict__ C, int M, int Nc, int K)
{
    int n = blockIdx.x * 64 + threadIdx.x;
    int m0 = blockIdx.y * 8;
    if (n >= Nc || m0 >= M) return;
    const float* a = A + (size_t)m0 * lda;
    float s[8];
#pragma unroll
    for (int r = 0; r < 8; r++) s[r] = 0.f;
    for (int k = 0; k < K; k++) {
        float w = W[(size_t)k * Nc + n];
#pragma unroll
        for (int r = 0; r < 8; r++) s[r] += a[(size_t)r * lda + k] * w;
    }
    float bv = bias[n];
#pragma unroll
    for (int r = 0; r < 8; r++)
        C[(size_t)(m0 + r) * Nc + n] = s[r] + bv;
}

// ---------------- fused GATv2, 2-stream + prefetch pipeline ----------------
__global__ void __launch_bounds__(128) gat_kernel(
    const float* __restrict__ xl, const float* __restrict__ xr,
    const float* __restrict__ att, const float* __restrict__ bias,
    float* __restrict__ out, __half* __restrict__ out16, int mode)
{
    int dst = blockIdx.x;
    int w = threadIdx.x >> 5;
    int l = threadIdx.x & 31;
    int start = g_off[dst];
    int end   = g_off[dst + 1];

    float4 xrr  = ((const float4*)(xr  + (size_t)dst * HC + w * CC))[l];
    float4 attr = ((const float4*)(att + w * CC))[l];

    float mx0 = -1e30f, den0 = 0.f;
    float4 A0 = make_float4(0.f, 0.f, 0.f, 0.f);
    float mx1 = -1e30f, den1 = 0.f;
    float4 A1 = make_float4(0.f, 0.f, 0.f, 0.f);

    const float* xb = xl + w * CC;

    for (int c0 = start; c0 < end; c0 += 32) {
        int myi = c0 + l;
        int mysrc = (myi < end) ? g_srcv[myi] : 0;
        int lim = end - c0; if (lim > 32) lim = 32;

        float4 xv0, xv1;
        {
            int s = __shfl_sync(0xffffffffu, mysrc, 0);
            xv0 = ((const float4*)(xb + (size_t)s * HC))[l];
        }
        if (lim > 1) {
            int s = __shfl_sync(0xffffffffu, mysrc, 1);
            xv1 = ((const float4*)(xb + (size_t)s * HC))[l];
        }

        for (int jj = 0; jj < lim; jj += 2) {
            float4 cv0 = xv0, cv1 = xv1;
            bool has1 = (jj + 1 < lim);
            int nj = jj + 2;
            if (nj < lim) {
                int s = __shfl_sync(0xffffffffu, mysrc, nj);
                xv0 = ((const float4*)(xb + (size_t)s * HC))[l];
                if (nj + 1 < lim) {
                    int s2 = __shfl_sync(0xffffffffu, mysrc, nj + 1);
                    xv1 = ((const float4*)(xb + (size_t)s2 * HC))[l];
                }
            }
            {
                float v0 = cv0.x + xrr.x; v0 = (v0 > 0.f) ? v0 : 0.2f * v0;
                float v1 = cv0.y + xrr.y; v1 = (v1 > 0.f) ? v1 : 0.2f * v1;
                float v2 = cv0.z + xrr.z; v2 = (v2 > 0.f) ? v2 : 0.2f * v2;
                float v3 = cv0.w + xrr.w; v3 = (v3 > 0.f) ? v3 : 0.2f * v3;
                float a = v0 * attr.x + v1 * attr.y + v2 * attr.z + v3 * attr.w;
#pragma unroll
                for (int o = 16; o; o >>= 1) a += __shfl_xor_sync(0xffffffffu, a, o);
                float nm = fmaxf(mx0, a);
                float sc = __expf(mx0 - nm);
                float ew = __expf(a - nm);
                den0 = den0 * sc + ew;
                A0.x = A0.x * sc + ew * cv0.x;
                A0.y = A0.y * sc + ew * cv0.y;
                A0.z = A0.z * sc + ew * cv0.z;
                A0.w = A0.w * sc + ew * cv0.w;
                mx0 = nm;
            }
            if (has1) {
                float v0 = cv1.x + xrr.x; v0 = (v0 > 0.f) ? v0 : 0.2f * v0;
                float v1 = cv1.y + xrr.y; v1 = (v1 > 0.f) ? v1 : 0.2f * v1;
                float v2 = cv1.z + xrr.z; v2 = (v2 > 0.f) ? v2 : 0.2f * v2;
                float v3 = cv1.w + xrr.w; v3 = (v3 > 0.f) ? v3 : 0.2f * v3;
                float a = v0 * attr.x + v1 * attr.y + v2 * attr.z + v3 * attr.w;
#pragma unroll
                for (int o = 16; o; o >>= 1) a += __shfl_xor_sync(0xffffffffu, a, o);
                float nm = fmaxf(mx1, a);
                float sc = __expf(mx1 - nm);
                float ew = __expf(a - nm);
                den1 = den1 * sc + ew;
                A1.x = A1.x * sc + ew * cv1.x;
                A1.y = A1.y * sc + ew * cv1.y;
                A1.z = A1.z * sc + ew * cv1.z;
                A1.w = A1.w * sc + ew * cv1.w;
                mx1 = nm;
            }
        }
    }

    float nm = fmaxf(mx0, mx1);
    float s0 = __expf(mx0 - nm), s1 = __expf(mx1 - nm);
    float den = den0 * s0 + den1 * s1;
    float4 acc;
    acc.x = A0.x * s0 + A1.x * s1;
    acc.y = A0.y * s0 + A1.y * s1;
    acc.z = A0.z * s0 + A1.z * s1;
    acc.w = A0.w * s0 + A1.w * s1;

    float inv = 1.0f / (den + 1e-16f);
    float4 bv = ((const float4*)(bias + w * CC))[l];
    float v[4];
    v[0] = acc.x * inv + bv.x;
    v[1] = acc.y * inv + bv.y;
    v[2] = acc.z * inv + bv.z;
    v[3] = acc.w * inv + bv.w;

    if (mode == 0) {
        float g0 = 0.5f * v[0] * (1.0f + erff(v[0] * 0.70710678118654752f));
        float g1 = 0.5f * v[1] * (1.0f + erff(v[1] * 0.70710678118654752f));
        float g2 = 0.5f * v[2] * (1.0f + erff(v[2] * 0.70710678118654752f));
        float g3 = 0.5f * v[3] * (1.0f + erff(v[3] * 0.70710678118654752f));
        __half2 H0 = {__float2half_rn(g0), __float2half_rn(g1)};
        __half2 H1 = {__float2half_rn(g2), __float2half_rn(g3)};
        *(uint2*)(out16 + (size_t)dst * HC + w * CC + 4 * l) =
            make_uint2(*(unsigned*)&H0, *(unsigned*)&H1);
    } else {
        float sq = v[0] * v[0] + v[1] * v[1] + v[2] * v[2] + v[3] * v[3];
#pragma unroll
        for (int o = 16; o; o >>= 1) sq += __shfl_xor_sync(0xffffffffu, sq, o);
        __shared__ float red[4];
        if (l == 0) red[w] = sq;
        __syncthreads();
        float tot = red[0] + red[1] + red[2] + red[3];
        if (threadIdx.x == 0) out[(size_t)dst * D1] = sqrtf(1.0f + tot);
        float* op = out + (size_t)dst * D1 + 1 + w * CC + 4 * l;
        op[0] = v[0]; op[1] = v[1]; op[2] = v[2]; op[3] = v[3];
    }
}

// ---------------- centroid per batch ----------------
__global__ void __launch_bounds__(256) centroid_kernel(
    const float* __restrict__ h3, float* __restrict__ gm)
{
    int b = blockIdx.x;
    __shared__ float avg[D1];
    const float* basep = h3 + (size_t)b * 128 * D1;
    for (int c = threadIdx.x; c < D1; c += blockDim.x) {
        float s = 0.f;
        for (int r = 0; r < 128; r++) s += basep[(size_t)r * D1 + c];
        avg[c] = s * (1.0f / 128.0f);
    }
    __syncthreads();
    float loc = 0.f;
    for (int c = threadIdx.x; c < D1; c += blockDim.x) {
        float a = avg[c];
        loc += (c == 0) ? -a * a : a * a;
    }
#pragma unroll
    for (int o = 16; o; o >>= 1) loc += __shfl_xor_sync(0xffffffffu, loc, o);
    __shared__ float red[8];
    int w = threadIdx.x >> 5, l = threadIdx.x & 31;
    if (l == 0) red[w] = loc;
    __syncthreads();
    __shared__ float s_invden;
    if (threadIdx.x == 0) {
        float inner = 0.f;
        for (int i = 0; i < 8; i++) inner += red[i];
        s_invden = 1.0f / sqrtf(fmaxf(-inner, 1e-8f));
    }
    __syncthreads();
    float invd = s_invden;
    for (int c = threadIdx.x; c < D1; c += blockDim.x)
        gm[(size_t)b * D1 + c] = avg[c] * invd;
}

// ---------------- llin epilogue (standalone) ----------------
__global__ void __launch_bounds__(256) llin_post_kernel(
    const float* __restrict__ zin, float* __restrict__ zout,
    const float* __restrict__ sptr, int D)
{
    int b = blockIdx.x;
    const float* row = zin + (size_t)b * D;
    float loc = 0.f;
    for (int c = 1 + threadIdx.x; c < D; c += blockDim.x) { float v = row[c]; loc += v * v; }
#pragma unroll
    for (int o = 16; o; o >>= 1) loc += __shfl_xor_sync(0xffffffffu, loc, o);
    __shared__ float red[8];
    int w = threadIdx.x >> 5, l = threadIdx.x & 31;
    if (l == 0) red[w] = loc;
    __syncthreads();
    __shared__ float s_t, s_scale;
    if (threadIdx.x == 0) {
        float sq = 0.f;
        for (int i = 0; i < 8; i++) sq += red[i];
        sq = fmaxf(sq, 1e-8f);
        float z0 = row[0];
        float t = (1.0f / (1.0f + expf(-z0))) * expf(*sptr) + 1.1f;
        s_t = t;
        s_scale = sqrtf((t * t - 1.0f) / sq);
    }
    __syncthreads();
    if (threadIdx.x == 0) zout[(size_t)b * D] = s_t;
    float sc = s_scale;
    for (int c = 1 + threadIdx.x; c < D; c += blockDim.x)
        zout[(size_t)b * D + c] = row[c] * sc;
}

// ---------------- fused llin + gelu + add_time (za -> z2) ----------------
// z1 = llin(za); z2 = add_time(gelu(z1[1:]))   all per-row, one kernel
__global__ void __launch_bounds__(256) llin_gelu_kernel(
    const float* __restrict__ za, float* __restrict__ z2,
    const float* __restrict__ sptr, int D)
{
    int b = blockIdx.x;
    const float* row = za + (size_t)b * D;
    float* orow = z2 + (size_t)b * D;
    int w = threadIdx.x >> 5, l = threadIdx.x & 31;
    __shared__ float red[8];

    // pass 1: norm of za[1:]
    float loc = 0.f;
    for (int c = 1 + threadIdx.x; c < D; c += blockDim.x) { float v = row[c]; loc += v * v; }
#pragma unroll
    for (int o = 16; o; o >>= 1) loc += __shfl_xor_sync(0xffffffffu, loc, o);
    if (l == 0) red[w] = loc;
    __syncthreads();
    __shared__ float s_scale;
    if (threadIdx.x == 0) {
        float sq = 0.f;
        for (int i = 0; i < 8; i++) sq += red[i];
        sq = fmaxf(sq, 1e-8f);
        float z0 = row[0];
        float t = (1.0f / (1.0f + expf(-z0))) * expf(*sptr) + 1.1f;
        s_scale = sqrtf((t * t - 1.0f) / sq);
    }
    __syncthreads();
    float sc = s_scale;

    // pass 2: g = gelu(za[c]*sc), write, accumulate g^2
    float loc2 = 0.f;
    for (int c = 1 + threadIdx.x; c < D; c += blockDim.x) {
        float z1 = row[c] * sc;
        float g = 0.5f * z1 * (1.0f + erff(z1 * 0.70710678118654752f));
        orow[c] = g;
        loc2 += g * g;
    }
#pragma unroll
    for (int o = 16; o; o >>= 1) loc2 += __shfl_xor_sync(0xffffffffu, loc2, o);
    __syncthreads();
    if (l == 0) red[w] = loc2;
    __syncthreads();
    if (threadIdx.x == 0) {
        float tot = 0.f;
        for (int i = 0; i < 8; i++) tot += red[i];
        orow[0] = sqrtf(1.0f + tot);
    }
}

// ---------------- launch ----------------
extern "C" void kernel_launch(void* const* d_in, const int* in_sizes, int n_in,
                              void* d_out, int out_size)
{
    const float* x  = (const float*)d_in[0];
    const int*   ei = (const int*)d_in[1];
    int base = 2;
    if (n_in > 2 && in_sizes[2] == 1) base = 3;

    const float* Wl1   = (const float*)d_in[base + 0];
    const float* bl1   = (const float*)d_in[base + 1];
    const float* Wr1   = (const float*)d_in[base + 2];
    const float* br1   = (const float*)d_in[base + 3];
    const float* att1  = (const float*)d_in[base + 4];
    const float* bias1 = (const float*)d_in[base + 5];
    const float* Wl2   = (const float*)d_in[base + 6];
    const float* bl2   = (const float*)d_in[base + 7];
    const float* Wr2   = (const float*)d_in[base + 8];
    const float* br2   = (const float*)d_in[base + 9];
    const float* att2  = (const float*)d_in[base + 10];
    const float* bias2 = (const float*)d_in[base + 11];
    const float* Wa    = (const float*)d_in[base + 12];
    const float* ba    = (const float*)d_in[base + 13];
    const float* sa    = (const float*)d_in[base + 14];
    const float* Wb    = (const float*)d_in[base + 15];
    const float* bb    = (const float*)d_in[base + 16];
    const float* sb    = (const float*)d_in[base + 17];
    const float* Wf    = (const float*)d_in[base + 18];
    const float* bf    = (const float*)d_in[base + 19];
    const float* sf    = (const float*)d_in[base + 20];

    float* out = (float*)d_out;

    void* p;
    cudaGetSymbolAddress(&p, g_xl); float* pxl = (float*)p;
    cudaGetSymbolAddress(&p, g_xr); float* pxr = (float*)p;
    cudaGetSymbolAddress(&p, g_h3); float* ph3 = (float*)p;
    cudaGetSymbolAddress(&p, g_za); float* pza = (float*)p;
    cudaGetSymbolAddress(&p, g_z2); float* pz2 = (float*)p;
    cudaGetSymbolAddress(&p, g_zb); float* pzb = (float*)p;
    cudaGetSymbolAddress(&p, g_z3); float* pz3 = (float*)p;
    cudaGetSymbolAddress(&p, g_zf); float* pzf = (float*)p;
    cudaGetSymbolAddress(&p, g_A16); __half* pA  = (__half*)p;
    cudaGetSymbolAddress(&p, g_W1t); __half* pW1 = (__half*)p;
    cudaGetSymbolAddress(&p, g_W2t); __half* pW2 = (__half*)p;
    cudaGetSymbolAddress(&p, g_W3t); __half* pW3 = (__half*)p;
    cudaGetSymbolAddress(&p, g_W4t); __half* pW4 = (__half*)p;

    static bool attr_set = false;
    if (!attr_set) {
        cudaFuncSetAttribute(gemm_dual_kernel,
                             cudaFuncAttributeMaxDynamicSharedMemorySize, GEMM_SMEM);
        cudaFuncSetAttribute(scatter_gemm_kernel,
                             cudaFuncAttributeMaxDynamicSharedMemorySize, GEMM_SMEM);
        attr_set = true;
    }

    // L1: convA + splitWT(Wl1,Wr1,Wl2,Wr2) + hist   (9216 + 576 = 9792 blocks)
    prep_kernel<<<9792, 256>>>(x, ei, Wl1, Wr1, Wl2, Wr2, pA);
    // L2: scan (also re-zeros deg)
    scan_kernel<<<1, 1024>>>();
    // L3: scatter + layer-1 dual GEMM
    scatter_gemm_kernel<<<576 + 1024, 256, GEMM_SMEM>>>(ei, pA, pW1, pW2, bl1, br1, pxl, pxr);
    // L4: layer-1 GAT
    gat_kernel<<<NV, 128>>>(pxl, pxr, att1, bias1, nullptr, pA, 0);

    // layer 2 (W3/W4 already transposed by prep)
    gemm_dual_kernel<<<dim3(8 * 128), 256, GEMM_SMEM>>>(pA, pW3, pW4, bl2, br2, pxl, pxr);
    gat_kernel<<<NV, 128>>>(pxl, pxr, att2, bias2, ph3, nullptr, 1);

    // centroid -> second half of output
    centroid_kernel<<<BB, 256>>>(ph3, out + (size_t)BB * D1);

    // MLP head (8 rows/thread tail GEMMs; fused llin+gelu)
    gemm_small_kernel<<<dim3((DA + 63) / 64, BB / 8), 64>>>(ph3, 128 * D1, Wa, ba, pza, BB, DA, D1);
    llin_gelu_kernel<<<BB, 256>>>(pza, pz2, sa, DA);
    gemm_small_kernel<<<dim3((D1 + 63) / 64, BB / 8), 64>>>(pz2, DA, Wb, bb, pzb, BB, D1, DA);
    llin_post_kernel<<<BB, 256>>>(pzb, pz3, sb, D1);
    gemm_small_kernel<<<dim3((D1 + 63) / 64, BB / 8), 64>>>(pz3, D1, Wf, bf, pzf, BB, D1, D1);
    llin_post_kernel<<<BB, 256>>>(pzf, out, sf, D1);

    (void)out_size;
}

// round 13
// speedup vs baseline: 1.1441x; 1.1441x over previous
#include <cuda_runtime.h>
#include <cuda_fp16.h>
#include <stdint.h>
#include <math.h>

// ---------------- problem constants ----------------
constexpr int NV   = 16384;
constexpr int EDG  = 131072;
constexpr int ETOT = EDG + NV;
constexpr int HC   = 512;
constexpr int CC   = 128;
constexpr int D1   = 513;
constexpr int BB   = 128;
constexpr int DA   = 2049;

// ---------------- device scratch ----------------
__device__ float g_xl[NV * HC];
__device__ float g_xr[NV * HC];
__device__ float g_h3[NV * D1];
__device__ int   g_deg[NV];          // zero-initialized; re-zeroed by scan each run
__device__ int   g_off[NV + 1];
__device__ int   g_cur[NV];
__device__ int   g_srcv[ETOT];
__device__ float g_za[BB * DA];
__device__ float g_z2[BB * DA];
__device__ float g_zb[BB * D1];
__device__ float g_z3[BB * D1];
__device__ float g_zf[BB * D1];
__device__ __half g_A16[NV * HC];
__device__ __half g_W1t[HC * HC];
__device__ __half g_W2t[HC * HC];
__device__ __half g_W3t[HC * HC];    // layer-2 Wl^T
__device__ __half g_W4t[HC * HC];    // layer-2 Wr^T

// ---------------- helpers ----------------
__device__ __forceinline__ void ldmat_x4(unsigned (&r)[4], unsigned addr) {
    asm volatile("ldmatrix.sync.aligned.m8n8.x4.shared.b16 {%0,%1,%2,%3}, [%4];"
        : "=r"(r[0]), "=r"(r[1]), "=r"(r[2]), "=r"(r[3]) : "r"(addr));
}
__device__ __forceinline__ void ldmat_x2(unsigned (&r)[2], unsigned addr) {
    asm volatile("ldmatrix.sync.aligned.m8n8.x2.shared.b16 {%0,%1}, [%2];"
        : "=r"(r[0]), "=r"(r[1]) : "r"(addr));
}
__device__ __forceinline__ void mma16816h(float (&d)[4], const unsigned (&a)[4], const unsigned (&b)[2]) {
    asm volatile("mma.sync.aligned.m16n8k16.row.col.f32.f16.f16.f32 "
        "{%0,%1,%2,%3},{%4,%5,%6,%7},{%8,%9},{%0,%1,%2,%3};"
        : "+f"(d[0]), "+f"(d[1]), "+f"(d[2]), "+f"(d[3])
        : "r"(a[0]), "r"(a[1]), "r"(a[2]), "r"(a[3]), "r"(b[0]), "r"(b[1]));
}
__device__ __forceinline__ unsigned smem_u32(const void* p) {
    return (unsigned)__cvta_generic_to_shared(p);
}
__device__ __forceinline__ void cp16(unsigned saddr, const void* g) {
    asm volatile("cp.async.cg.shared.global [%0], [%1], 16;" :: "r"(saddr), "l"(g));
}

// ---------------- shared bodies ----------------
__device__ __forceinline__ void convA_body(int i, const float* __restrict__ A, int lda,
                                           __half* __restrict__ Ah) {
    int row = i >> 7, c4 = (i & 127) * 4;
    const float* ap = A + (size_t)row * lda + c4;
    __half2 H0 = {__float2half_rn(ap[0]), __float2half_rn(ap[1])};
    __half2 H1 = {__float2half_rn(ap[2]), __float2half_rn(ap[3])};
    *(uint2*)&Ah[(size_t)row * 512 + c4] = make_uint2(*(unsigned*)&H0, *(unsigned*)&H1);
}

__device__ __forceinline__ void splitWT_body(int tile, int tid,
                                             const float* __restrict__ W,
                                             __half* __restrict__ T,
                                             float (*t)[33]) {
    int bn = (tile & 15) * 32, bk = (tile >> 4) * 32;
    int tx = tid & 31, ty = tid >> 5;
#pragma unroll
    for (int i = 0; i < 4; i++) {
        int k = bk + ty + i * 8;
        t[ty + i * 8][tx] = W[(size_t)k * 512 + bn + tx];
    }
    __syncthreads();
#pragma unroll
    for (int i = 0; i < 4; i++) {
        int n = bn + ty + i * 8;
        T[(size_t)n * 512 + bk + tx] = __float2half_rn(t[tx][ty + i * 8]);
    }
}

// ---------------- L1: fused prep (convA + 4x splitWT + hist) ----------------
__global__ void __launch_bounds__(256) prep_kernel(
    const float* __restrict__ x, const int* __restrict__ ei,
    const float* __restrict__ Wl1, const float* __restrict__ Wr1,
    const float* __restrict__ Wl2, const float* __restrict__ Wr2,
    __half* __restrict__ Ah)
{
    __shared__ float t[32][33];
    int b = blockIdx.x, tid = threadIdx.x;
    if (b < 8192) {
        convA_body(b * 256 + tid, x + 1, D1, Ah);
    } else if (b < 8448) {
        splitWT_body(b - 8192, tid, Wl1, g_W1t, t);
    } else if (b < 8704) {
        splitWT_body(b - 8448, tid, Wr1, g_W2t, t);
    } else if (b < 8960) {
        splitWT_body(b - 8704, tid, Wl2, g_W3t, t);
    } else if (b < 9216) {
        splitWT_body(b - 8960, tid, Wr2, g_W4t, t);
    } else {
        int i = (b - 9216) * 256 + tid;
        if (i < ETOT) {
            int dst = (i < EDG) ? ei[EDG + i] : (i - EDG);
            atomicAdd(&g_deg[dst], 1);
        }
    }
}

// ---------------- L2: scan (also re-zeros g_deg for next run) ----------------
__global__ void scan_kernel() {
    __shared__ int part[1024];
    int t = threadIdx.x;
    int loc[16];
    int s = 0;
#pragma unroll
    for (int i = 0; i < 16; i++) { loc[i] = s; s += g_deg[t * 16 + i]; }
    part[t] = s;
    __syncthreads();
    for (int d = 1; d < 1024; d <<= 1) {
        int v = (t >= d) ? part[t - d] : 0;
        __syncthreads();
        part[t] += v;
        __syncthreads();
    }
    int base = (t > 0) ? part[t - 1] : 0;
#pragma unroll
    for (int i = 0; i < 16; i++) {
        int o = base + loc[i];
        g_off[t * 16 + i] = o;
        g_cur[t * 16 + i] = o;
        g_deg[t * 16 + i] = 0;
    }
    if (t == 1023) g_off[NV] = part[1023];
}

// ---------------- GEMM body (fp16, fp32 accum, BK=64, dual-output) ----------
constexpr int ASTR    = 72;
constexpr int TILE_E  = 128 * ASTR;
constexpr int GEMM_SMEM = 2 * 2 * TILE_E * 2;  // 73728 B

__device__ __forceinline__ void gemm_body(
    int bx, const __half* __restrict__ Ah,
    const __half* __restrict__ W1, const __half* __restrict__ W2,
    const float* __restrict__ b1, const float* __restrict__ b2,
    float* __restrict__ C1, float* __restrict__ C2, __half* smem)
{
    const int tid  = threadIdx.x;
    const int lane = tid & 31;
    const int warp = tid >> 5;
    const int wm   = warp >> 2;
    const int wn   = warp & 3;
    const int bm   = (bx >> 3) * 128;
    const int sub  = bx & 7;
    const bool second = (sub >= 4);
    const int bn   = (sub & 3) * 128;

    const __half* Wt  = second ? W2 : W1;
    const float* bias = second ? b2 : b1;
    float* C          = second ? C2 : C1;

    const __half* gsrc[2] = { Ah + (size_t)bm * 512, Wt + (size_t)bn * 512 };

    float acc[4][4][4];
#pragma unroll
    for (int mt = 0; mt < 4; mt++)
#pragma unroll
        for (int nt = 0; nt < 4; nt++)
#pragma unroll
            for (int q = 0; q < 4; q++) acc[mt][nt][q] = 0.f;

    auto load_tile = [&](int buf, int k0) {
#pragma unroll
        for (int i = 0; i < 8; i++) {
            int id  = tid + i * 256;
            int arr = id >> 10;
            int w   = id & 1023;
            int r   = w >> 3;
            int c16 = w & 7;
            __half* s = smem + (buf * 2 + arr) * TILE_E;
            cp16(smem_u32(s + r * ASTR + c16 * 8),
                 gsrc[arr] + (size_t)r * 512 + k0 + c16 * 8);
        }
        asm volatile("cp.async.commit_group;");
    };

    load_tile(0, 0);

    for (int t = 0; t < 8; t++) {
        int buf = t & 1;
        if (t < 7) load_tile(buf ^ 1, (t + 1) * 64);
        if (t < 7) asm volatile("cp.async.wait_group 1;");
        else       asm volatile("cp.async.wait_group 0;");
        __syncthreads();

        const __half* sA = smem + (buf * 2 + 0) * TILE_E;
        const __half* sB = smem + (buf * 2 + 1) * TILE_E;

#pragma unroll
        for (int ks = 0; ks < 4; ks++) {
            unsigned bf[4][2];
#pragma unroll
            for (int nt = 0; nt < 4; nt++) {
                int n = wn * 32 + nt * 8 + (lane & 7);
                int k = ks * 16 + ((lane >> 3) & 1) * 8;
                ldmat_x2(bf[nt], smem_u32(sB + n * ASTR + k));
            }
#pragma unroll
            for (int mt = 0; mt < 4; mt++) {
                int m = wm * 64 + mt * 16 + ((lane >> 3) & 1) * 8 + (lane & 7);
                int k = ks * 16 + ((lane >> 4) & 1) * 8;
                unsigned af[4];
                ldmat_x4(af, smem_u32(sA + m * ASTR + k));
#pragma unroll
                for (int nt = 0; nt < 4; nt++)
                    mma16816h(acc[mt][nt], af, bf[nt]);
            }
        }
        __syncthreads();
    }

    const int g  = lane >> 2;
    const int t4 = lane & 3;
#pragma unroll
    for (int mt = 0; mt < 4; mt++) {
#pragma unroll
        for (int nt = 0; nt < 4; nt++) {
            int row = bm + wm * 64 + mt * 16 + g;
            int col = bn + wn * 32 + nt * 8 + 2 * t4;
            float2 bv = *(const float2*)&bias[col];
            float2 o0 = make_float2(acc[mt][nt][0] + bv.x, acc[mt][nt][1] + bv.y);
            float2 o1 = make_float2(acc[mt][nt][2] + bv.x, acc[mt][nt][3] + bv.y);
            *(float2*)&C[(size_t)row * 512 + col] = o0;
            *(float2*)&C[(size_t)(row + 8) * 512 + col] = o1;
        }
    }
}

// ---------------- L3: fused scatter + dual GEMM ----------------
__global__ void __launch_bounds__(256, 2) scatter_gemm_kernel(
    const int* __restrict__ ei, const __half* __restrict__ Ah,
    const __half* __restrict__ W1, const __half* __restrict__ W2,
    const float* __restrict__ b1, const float* __restrict__ b2,
    float* __restrict__ C1, float* __restrict__ C2)
{
    extern __shared__ __half smem[];
    if (blockIdx.x < 576) {
        int i = blockIdx.x * 256 + threadIdx.x;
        if (i >= ETOT) return;
        int s, d;
        if (i < EDG) { s = ei[i]; d = ei[EDG + i]; }
        else         { s = d = i - EDG; }
        int p = atomicAdd(&g_cur[d], 1);
        g_srcv[p] = s;
        return;
    }
    gemm_body(blockIdx.x - 576, Ah, W1, W2, b1, b2, C1, C2, smem);
}

// standalone dual GEMM (layer 2)
__global__ void __launch_bounds__(256, 2) gemm_dual_kernel(
    const __half* __restrict__ Ah,
    const __half* __restrict__ W1, const __half* __restrict__ W2,
    const float* __restrict__ b1, const float* __restrict__ b2,
    float* __restrict__ C1, float* __restrict__ C2)
{
    extern __shared__ __half smem[];
    gemm_body(blockIdx.x, Ah, W1, W2, b1, b2, C1, C2, smem);
}

// ---------------- small-M GEMM (MLP tail): 4 rows/thread, 256-thread blocks -
__global__ void gemm_small_kernel(
    const float* __restrict__ A, int lda,
    const float* __restrict__ W,
    const float* __restrict__ bias,
    float* __restrict__ C, int M, int Nc, int K)
{
    int n = blockIdx.x * blockDim.x + threadIdx.x;
    int m0 = blockIdx.y * 4;
    if (n >= Nc || m0 >= M) return;
    const float* a0 = A + (size_t)m0 * lda;
    const float* a1 = a0 + lda;
    const float* a2 = a1 + lda;
    const float* a3 = a2 + lda;
    float s0 = 0.f, s1 = 0.f, s2 = 0.f, s3 = 0.f;
    for (int k = 0; k < K; k++) {
        float w = W[(size_t)k * Nc + n];
        s0 += a0[k] * w; s1 += a1[k] * w; s2 += a2[k] * w; s3 += a3[k] * w;
    }
    float bv = bias[n];
    C[(size_t)(m0 + 0) * Nc + n] = s0 + bv;
    C[(size_t)(m0 + 1) * Nc + n] = s1 + bv;
    C[(size_t)(m0 + 2) * Nc + n] = s2 + bv;
    C[(size_t)(m0 + 3) * Nc + n] = s3 + bv;
}

// ---------------- fused GATv2, 2-stream + prefetch pipeline ----------------
__global__ void __launch_bounds__(128) gat_kernel(
    const float* __restrict__ xl, const float* __restrict__ xr,
    const float* __restrict__ att, const float* __restrict__ bias,
    float* __restrict__ out, __half* __restrict__ out16, int mode)
{
    int dst = blockIdx.x;
    int w = threadIdx.x >> 5;
    int l = threadIdx.x & 31;
    int start = g_off[dst];
    int end   = g_off[dst + 1];

    float4 xrr  = ((const float4*)(xr  + (size_t)dst * HC + w * CC))[l];
    float4 attr = ((const float4*)(att + w * CC))[l];

    float mx0 = -1e30f, den0 = 0.f;
    float4 A0 = make_float4(0.f, 0.f, 0.f, 0.f);
    float mx1 = -1e30f, den1 = 0.f;
    float4 A1 = make_float4(0.f, 0.f, 0.f, 0.f);

    const float* xb = xl + w * CC;

    for (int c0 = start; c0 < end; c0 += 32) {
        int myi = c0 + l;
        int mysrc = (myi < end) ? g_srcv[myi] : 0;
        int lim = end - c0; if (lim > 32) lim = 32;

        float4 xv0, xv1;
        {
            int s = __shfl_sync(0xffffffffu, mysrc, 0);
            xv0 = ((const float4*)(xb + (size_t)s * HC))[l];
        }
        if (lim > 1) {
            int s = __shfl_sync(0xffffffffu, mysrc, 1);
            xv1 = ((const float4*)(xb + (size_t)s * HC))[l];
        }

        for (int jj = 0; jj < lim; jj += 2) {
            float4 cv0 = xv0, cv1 = xv1;
            bool has1 = (jj + 1 < lim);
            int nj = jj + 2;
            if (nj < lim) {
                int s = __shfl_sync(0xffffffffu, mysrc, nj);
                xv0 = ((const float4*)(xb + (size_t)s * HC))[l];
                if (nj + 1 < lim) {
                    int s2 = __shfl_sync(0xffffffffu, mysrc, nj + 1);
                    xv1 = ((const float4*)(xb + (size_t)s2 * HC))[l];
                }
            }
            {
                float v0 = cv0.x + xrr.x; v0 = (v0 > 0.f) ? v0 : 0.2f * v0;
                float v1 = cv0.y + xrr.y; v1 = (v1 > 0.f) ? v1 : 0.2f * v1;
                float v2 = cv0.z + xrr.z; v2 = (v2 > 0.f) ? v2 : 0.2f * v2;
                float v3 = cv0.w + xrr.w; v3 = (v3 > 0.f) ? v3 : 0.2f * v3;
                float a = v0 * attr.x + v1 * attr.y + v2 * attr.z + v3 * attr.w;
#pragma unroll
                for (int o = 16; o; o >>= 1) a += __shfl_xor_sync(0xffffffffu, a, o);
                float nm = fmaxf(mx0, a);
                float sc = __expf(mx0 - nm);
                float ew = __expf(a - nm);
                den0 = den0 * sc + ew;
                A0.x = A0.x * sc + ew * cv0.x;
                A0.y = A0.y * sc + ew * cv0.y;
                A0.z = A0.z * sc + ew * cv0.z;
                A0.w = A0.w * sc + ew * cv0.w;
                mx0 = nm;
            }
            if (has1) {
                float v0 = cv1.x + xrr.x; v0 = (v0 > 0.f) ? v0 : 0.2f * v0;
                float v1 = cv1.y + xrr.y; v1 = (v1 > 0.f) ? v1 : 0.2f * v1;
                float v2 = cv1.z + xrr.z; v2 = (v2 > 0.f) ? v2 : 0.2f * v2;
                float v3 = cv1.w + xrr.w; v3 = (v3 > 0.f) ? v3 : 0.2f * v3;
                float a = v0 * attr.x + v1 * attr.y + v2 * attr.z + v3 * attr.w;
#pragma unroll
                for (int o = 16; o; o >>= 1) a += __shfl_xor_sync(0xffffffffu, a, o);
                float nm = fmaxf(mx1, a);
                float sc = __expf(mx1 - nm);
                float ew = __expf(a - nm);
                den1 = den1 * sc + ew;
                A1.x = A1.x * sc + ew * cv1.x;
                A1.y = A1.y * sc + ew * cv1.y;
                A1.z = A1.z * sc + ew * cv1.z;
                A1.w = A1.w * sc + ew * cv1.w;
                mx1 = nm;
            }
        }
    }

    float nm = fmaxf(mx0, mx1);
    float s0 = __expf(mx0 - nm), s1 = __expf(mx1 - nm);
    float den = den0 * s0 + den1 * s1;
    float4 acc;
    acc.x = A0.x * s0 + A1.x * s1;
    acc.y = A0.y * s0 + A1.y * s1;
    acc.z = A0.z * s0 + A1.z * s1;
    acc.w = A0.w * s0 + A1.w * s1;

    float inv = 1.0f / (den + 1e-16f);
    float4 bv = ((const float4*)(bias + w * CC))[l];
    float v[4];
    v[0] = acc.x * inv + bv.x;
    v[1] = acc.y * inv + bv.y;
    v[2] = acc.z * inv + bv.z;
    v[3] = acc.w * inv + bv.w;

    if (mode == 0) {
        float g0 = 0.5f * v[0] * (1.0f + erff(v[0] * 0.70710678118654752f));
        float g1 = 0.5f * v[1] * (1.0f + erff(v[1] * 0.70710678118654752f));
        float g2 = 0.5f * v[2] * (1.0f + erff(v[2] * 0.70710678118654752f));
        float g3 = 0.5f * v[3] * (1.0f + erff(v[3] * 0.70710678118654752f));
        __half2 H0 = {__float2half_rn(g0), __float2half_rn(g1)};
        __half2 H1 = {__float2half_rn(g2), __float2half_rn(g3)};
        *(uint2*)(out16 + (size_t)dst * HC + w * CC + 4 * l) =
            make_uint2(*(unsigned*)&H0, *(unsigned*)&H1);
    } else {
        float sq = v[0] * v[0] + v[1] * v[1] + v[2] * v[2] + v[3] * v[3];
#pragma unroll
        for (int o = 16; o; o >>= 1) sq += __shfl_xor_sync(0xffffffffu, sq, o);
        __shared__ float red[4];
        if (l == 0) red[w] = sq;
        __syncthreads();
        float tot = red[0] + red[1] + red[2] + red[3];
        if (threadIdx.x == 0) out[(size_t)dst * D1] = sqrtf(1.0f + tot);
        float* op = out + (size_t)dst * D1 + 1 + w * CC + 4 * l;
        op[0] = v[0]; op[1] = v[1]; op[2] = v[2]; op[3] = v[3];
    }
}

// ---------------- centroid per batch ----------------
__global__ void __launch_bounds__(256) centroid_kernel(
    const float* __restrict__ h3, float* __restrict__ gm)
{
    int b = blockIdx.x;
    __shared__ float avg[D1];
    const float* basep = h3 + (size_t)b * 128 * D1;
    for (int c = threadIdx.x; c < D1; c += blockDim.x) {
        float s = 0.f;
        for (int r = 0; r < 128; r++) s += basep[(size_t)r * D1 + c];
        avg[c] = s * (1.0f / 128.0f);
    }
    __syncthreads();
    float loc = 0.f;
    for (int c = threadIdx.x; c < D1; c += blockDim.x) {
        float a = avg[c];
        loc += (c == 0) ? -a * a : a * a;
    }
#pragma unroll
    for (int o = 16; o; o >>= 1) loc += __shfl_xor_sync(0xffffffffu, loc, o);
    __shared__ float red[8];
    int w = threadIdx.x >> 5, l = threadIdx.x & 31;
    if (l == 0) red[w] = loc;
    __syncthreads();
    __shared__ float s_invden;
    if (threadIdx.x == 0) {
        float inner = 0.f;
        for (int i = 0; i < 8; i++) inner += red[i];
        s_invden = 1.0f / sqrtf(fmaxf(-inner, 1e-8f));
    }
    __syncthreads();
    float invd = s_invden;
    for (int c = threadIdx.x; c < D1; c += blockDim.x)
        gm[(size_t)b * D1 + c] = avg[c] * invd;
}

// ---------------- llin epilogue (standalone) ----------------
__global__ void __launch_bounds__(256) llin_post_kernel(
    const float* __restrict__ zin, float* __restrict__ zout,
    const float* __restrict__ sptr, int D)
{
    int b = blockIdx.x;
    const float* row = zin + (size_t)b * D;
    float loc = 0.f;
    for (int c = 1 + threadIdx.x; c < D; c += blockDim.x) { float v = row[c]; loc += v * v; }
#pragma unroll
    for (int o = 16; o; o >>= 1) loc += __shfl_xor_sync(0xffffffffu, loc, o);
    __shared__ float red[8];
    int w = threadIdx.x >> 5, l = threadIdx.x & 31;
    if (l == 0) red[w] = loc;
    __syncthreads();
    __shared__ float s_t, s_scale;
    if (threadIdx.x == 0) {
        float sq = 0.f;
        for (int i = 0; i < 8; i++) sq += red[i];
        sq = fmaxf(sq, 1e-8f);
        float z0 = row[0];
        float t = (1.0f / (1.0f + expf(-z0))) * expf(*sptr) + 1.1f;
        s_t = t;
        s_scale = sqrtf((t * t - 1.0f) / sq);
    }
    __syncthreads();
    if (threadIdx.x == 0) zout[(size_t)b * D] = s_t;
    float sc = s_scale;
    for (int c = 1 + threadIdx.x; c < D; c += blockDim.x)
        zout[(size_t)b * D + c] = row[c] * sc;
}

// ---------------- fused llin + gelu + add_time (za -> z2) ----------------
__global__ void __launch_bounds__(256) llin_gelu_kernel(
    const float* __restrict__ za, float* __restrict__ z2,
    const float* __restrict__ sptr, int D)
{
    int b = blockIdx.x;
    const float* row = za + (size_t)b * D;
    float* orow = z2 + (size_t)b * D;
    int w = threadIdx.x >> 5, l = threadIdx.x & 31;
    __shared__ float red[8];

    float loc = 0.f;
    for (int c = 1 + threadIdx.x; c < D; c += blockDim.x) { float v = row[c]; loc += v * v; }
#pragma unroll
    for (int o = 16; o; o >>= 1) loc += __shfl_xor_sync(0xffffffffu, loc, o);
    if (l == 0) red[w] = loc;
    __syncthreads();
    __shared__ float s_scale;
    if (threadIdx.x == 0) {
        float sq = 0.f;
        for (int i = 0; i < 8; i++) sq += red[i];
        sq = fmaxf(sq, 1e-8f);
        float z0 = row[0];
        float t = (1.0f / (1.0f + expf(-z0))) * expf(*sptr) + 1.1f;
        s_scale = sqrtf((t * t - 1.0f) / sq);
    }
    __syncthreads();
    float sc = s_scale;

    float loc2 = 0.f;
    for (int c = 1 + threadIdx.x; c < D; c += blockDim.x) {
        float z1 = row[c] * sc;
        float g = 0.5f * z1 * (1.0f + erff(z1 * 0.70710678118654752f));
        orow[c] = g;
        loc2 += g * g;
    }
#pragma unroll
    for (int o = 16; o; o >>= 1) loc2 += __shfl_xor_sync(0xffffffffu, loc2, o);
    __syncthreads();
    if (l == 0) red[w] = loc2;
    __syncthreads();
    if (threadIdx.x == 0) {
        float tot = 0.f;
        for (int i = 0; i < 8; i++) tot += red[i];
        orow[0] = sqrtf(1.0f + tot);
    }
}

// ---------------- launch ----------------
extern "C" void kernel_launch(void* const* d_in, const int* in_sizes, int n_in,
                              void* d_out, int out_size)
{
    const float* x  = (const float*)d_in[0];
    const int*   ei = (const int*)d_in[1];
    int base = 2;
    if (n_in > 2 && in_sizes[2] == 1) base = 3;

    const float* Wl1   = (const float*)d_in[base + 0];
    const float* bl1   = (const float*)d_in[base + 1];
    const float* Wr1   = (const float*)d_in[base + 2];
    const float* br1   = (const float*)d_in[base + 3];
    const float* att1  = (const float*)d_in[base + 4];
    const float* bias1 = (const float*)d_in[base + 5];
    const float* Wl2   = (const float*)d_in[base + 6];
    const float* bl2   = (const float*)d_in[base + 7];
    const float* Wr2   = (const float*)d_in[base + 8];
    const float* br2   = (const float*)d_in[base + 9];
    const float* att2  = (const float*)d_in[base + 10];
    const float* bias2 = (const float*)d_in[base + 11];
    const float* Wa    = (const float*)d_in[base + 12];
    const float* ba    = (const float*)d_in[base + 13];
    const float* sa    = (const float*)d_in[base + 14];
    const float* Wb    = (const float*)d_in[base + 15];
    const float* bb    = (const float*)d_in[base + 16];
    const float* sb    = (const float*)d_in[base + 17];
    const float* Wf    = (const float*)d_in[base + 18];
    const float* bf    = (const float*)d_in[base + 19];
    const float* sf    = (const float*)d_in[base + 20];

    float* out = (float*)d_out;

    void* p;
    cudaGetSymbolAddress(&p, g_xl); float* pxl = (float*)p;
    cudaGetSymbolAddress(&p, g_xr); float* pxr = (float*)p;
    cudaGetSymbolAddress(&p, g_h3); float* ph3 = (float*)p;
    cudaGetSymbolAddress(&p, g_za); float* pza = (float*)p;
    cudaGetSymbolAddress(&p, g_z2); float* pz2 = (float*)p;
    cudaGetSymbolAddress(&p, g_zb); float* pzb = (float*)p;
    cudaGetSymbolAddress(&p, g_z3); float* pz3 = (float*)p;
    cudaGetSymbolAddress(&p, g_zf); float* pzf = (float*)p;
    cudaGetSymbolAddress(&p, g_A16); __half* pA  = (__half*)p;
    cudaGetSymbolAddress(&p, g_W1t); __half* pW1 = (__half*)p;
    cudaGetSymbolAddress(&p, g_W2t); __half* pW2 = (__half*)p;
    cudaGetSymbolAddress(&p, g_W3t); __half* pW3 = (__half*)p;
    cudaGetSymbolAddress(&p, g_W4t); __half* pW4 = (__half*)p;

    static bool attr_set = false;
    if (!attr_set) {
        cudaFuncSetAttribute(gemm_dual_kernel,
                             cudaFuncAttributeMaxDynamicSharedMemorySize, GEMM_SMEM);
        cudaFuncSetAttribute(scatter_gemm_kernel,
                             cudaFuncAttributeMaxDynamicSharedMemorySize, GEMM_SMEM);
        attr_set = true;
    }

    // L1: convA + splitWT(Wl1,Wr1,Wl2,Wr2) + hist   (9216 + 576 = 9792 blocks)
    prep_kernel<<<9792, 256>>>(x, ei, Wl1, Wr1, Wl2, Wr2, pA);
    // L2: scan (also re-zeros deg)
    scan_kernel<<<1, 1024>>>();
    // L3: scatter + layer-1 dual GEMM
    scatter_gemm_kernel<<<576 + 1024, 256, GEMM_SMEM>>>(ei, pA, pW1, pW2, bl1, br1, pxl, pxr);
    // L4: layer-1 GAT
    gat_kernel<<<NV, 128>>>(pxl, pxr, att1, bias1, nullptr, pA, 0);

    // layer 2 (W3/W4 already transposed by prep)
    gemm_dual_kernel<<<dim3(8 * 128), 256, GEMM_SMEM>>>(pA, pW3, pW4, bl2, br2, pxl, pxr);
    gat_kernel<<<NV, 128>>>(pxl, pxr, att2, bias2, ph3, nullptr, 1);

    // centroid -> second half of output
    centroid_kernel<<<BB, 256>>>(ph3, out + (size_t)BB * D1);

    // MLP head (proven R11 tail-GEMM shape; fused llin+gelu kept)
    gemm_small_kernel<<<dim3((DA + 255) / 256, BB / 4), 256>>>(ph3, 128 * D1, Wa, ba, pza, BB, DA, D1);
    llin_gelu_kernel<<<BB, 256>>>(pza, pz2, sa, DA);
    gemm_small_kernel<<<dim3((D1 + 255) / 256, BB / 4), 256>>>(pz2, DA, Wb, bb, pzb, BB, D1, DA);
    llin_post_kernel<<<BB, 256>>>(pzb, pz3, sb, D1);
    gemm_small_kernel<<<dim3((D1 + 255) / 256, BB / 4), 256>>>(pz3, D1, Wf, bf, pzf, BB, D1, D1);
    llin_post_kernel<<<BB, 256>>>(pzf, out, sf, D1);

    (void)out_size;
}

// round 14
// speedup vs baseline: 1.1645x; 1.0178x over previous
#include <cuda_runtime.h>
#include <cuda_fp16.h>
#include <stdint.h>
#include <math.h>

// ---------------- problem constants ----------------
constexpr int NV   = 16384;
constexpr int EDG  = 131072;
constexpr int ETOT = EDG + NV;
constexpr int HC   = 512;
constexpr int CC   = 128;
constexpr int D1   = 513;
constexpr int BB   = 128;
constexpr int DA   = 2049;

// ---------------- device scratch ----------------
__device__ float g_xl[NV * HC];
__device__ float g_xr[NV * HC];
__device__ float g_h3[NV * D1];
__device__ int   g_deg[NV];          // zero-initialized; re-zeroed by scan each run
__device__ int   g_off[NV + 1];
__device__ int   g_cur[NV];
__device__ int   g_srcv[ETOT];
__device__ float g_za[BB * DA];
__device__ float g_z2[BB * DA];
__device__ float g_zb[BB * D1];
__device__ float g_z3[BB * D1];
__device__ float g_zf[BB * D1];
__device__ __half g_A16[NV * HC];
__device__ __half g_W1t[HC * HC];
__device__ __half g_W2t[HC * HC];
__device__ __half g_W3t[HC * HC];    // layer-2 Wl^T
__device__ __half g_W4t[HC * HC];    // layer-2 Wr^T

// ---------------- helpers ----------------
__device__ __forceinline__ void ldmat_x4(unsigned (&r)[4], unsigned addr) {
    asm volatile("ldmatrix.sync.aligned.m8n8.x4.shared.b16 {%0,%1,%2,%3}, [%4];"
        : "=r"(r[0]), "=r"(r[1]), "=r"(r[2]), "=r"(r[3]) : "r"(addr));
}
__device__ __forceinline__ void ldmat_x2(unsigned (&r)[2], unsigned addr) {
    asm volatile("ldmatrix.sync.aligned.m8n8.x2.shared.b16 {%0,%1}, [%2];"
        : "=r"(r[0]), "=r"(r[1]) : "r"(addr));
}
__device__ __forceinline__ void mma16816h(float (&d)[4], const unsigned (&a)[4], const unsigned (&b)[2]) {
    asm volatile("mma.sync.aligned.m16n8k16.row.col.f32.f16.f16.f32 "
        "{%0,%1,%2,%3},{%4,%5,%6,%7},{%8,%9},{%0,%1,%2,%3};"
        : "+f"(d[0]), "+f"(d[1]), "+f"(d[2]), "+f"(d[3])
        : "r"(a[0]), "r"(a[1]), "r"(a[2]), "r"(a[3]), "r"(b[0]), "r"(b[1]));
}
__device__ __forceinline__ unsigned smem_u32(const void* p) {
    return (unsigned)__cvta_generic_to_shared(p);
}
__device__ __forceinline__ void cp16(unsigned saddr, const void* g) {
    asm volatile("cp.async.cg.shared.global [%0], [%1], 16;" :: "r"(saddr), "l"(g));
}

// ---------------- shared bodies ----------------
__device__ __forceinline__ void convA_body(int i, const float* __restrict__ A, int lda,
                                           __half* __restrict__ Ah) {
    int row = i >> 7, c4 = (i & 127) * 4;
    const float* ap = A + (size_t)row * lda + c4;
    __half2 H0 = {__float2half_rn(ap[0]), __float2half_rn(ap[1])};
    __half2 H1 = {__float2half_rn(ap[2]), __float2half_rn(ap[3])};
    *(uint2*)&Ah[(size_t)row * 512 + c4] = make_uint2(*(unsigned*)&H0, *(unsigned*)&H1);
}

__device__ __forceinline__ void splitWT_body(int tile, int tid,
                                             const float* __restrict__ W,
                                             __half* __restrict__ T,
                                             float (*t)[33]) {
    int bn = (tile & 15) * 32, bk = (tile >> 4) * 32;
    int tx = tid & 31, ty = tid >> 5;
#pragma unroll
    for (int i = 0; i < 4; i++) {
        int k = bk + ty + i * 8;
        t[ty + i * 8][tx] = W[(size_t)k * 512 + bn + tx];
    }
    __syncthreads();
#pragma unroll
    for (int i = 0; i < 4; i++) {
        int n = bn + ty + i * 8;
        T[(size_t)n * 512 + bk + tx] = __float2half_rn(t[tx][ty + i * 8]);
    }
}

// ---------------- L1: fused prep (convA + 4x splitWT + hist) ----------------
__global__ void __launch_bounds__(256) prep_kernel(
    const float* __restrict__ x, const int* __restrict__ ei,
    const float* __restrict__ Wl1, const float* __restrict__ Wr1,
    const float* __restrict__ Wl2, const float* __restrict__ Wr2,
    __half* __restrict__ Ah)
{
    __shared__ float t[32][33];
    int b = blockIdx.x, tid = threadIdx.x;
    if (b < 8192) {
        convA_body(b * 256 + tid, x + 1, D1, Ah);
    } else if (b < 8448) {
        splitWT_body(b - 8192, tid, Wl1, g_W1t, t);
    } else if (b < 8704) {
        splitWT_body(b - 8448, tid, Wr1, g_W2t, t);
    } else if (b < 8960) {
        splitWT_body(b - 8704, tid, Wl2, g_W3t, t);
    } else if (b < 9216) {
        splitWT_body(b - 8960, tid, Wr2, g_W4t, t);
    } else {
        int i = (b - 9216) * 256 + tid;
        if (i < ETOT) {
            int dst = (i < EDG) ? ei[EDG + i] : (i - EDG);
            atomicAdd(&g_deg[dst], 1);
        }
    }
}

// ---------------- L2: scan (also re-zeros g_deg for next run) ----------------
__global__ void scan_kernel() {
    __shared__ int part[1024];
    int t = threadIdx.x;
    int loc[16];
    int s = 0;
#pragma unroll
    for (int i = 0; i < 16; i++) { loc[i] = s; s += g_deg[t * 16 + i]; }
    part[t] = s;
    __syncthreads();
    for (int d = 1; d < 1024; d <<= 1) {
        int v = (t >= d) ? part[t - d] : 0;
        __syncthreads();
        part[t] += v;
        __syncthreads();
    }
    int base = (t > 0) ? part[t - 1] : 0;
#pragma unroll
    for (int i = 0; i < 16; i++) {
        int o = base + loc[i];
        g_off[t * 16 + i] = o;
        g_cur[t * 16 + i] = o;
        g_deg[t * 16 + i] = 0;
    }
    if (t == 1023) g_off[NV] = part[1023];
}

// ---------------- GEMM body (fp16, fp32 accum, BK=64, dual-output) ----------
constexpr int ASTR    = 72;
constexpr int TILE_E  = 128 * ASTR;
constexpr int GEMM_SMEM = 2 * 2 * TILE_E * 2;  // 73728 B

__device__ __forceinline__ void gemm_body(
    int bx, const __half* __restrict__ Ah,
    const __half* __restrict__ W1, const __half* __restrict__ W2,
    const float* __restrict__ b1, const float* __restrict__ b2,
    float* __restrict__ C1, float* __restrict__ C2, __half* smem)
{
    const int tid  = threadIdx.x;
    const int lane = tid & 31;
    const int warp = tid >> 5;
    const int wm   = warp >> 2;
    const int wn   = warp & 3;
    const int bm   = (bx >> 3) * 128;
    const int sub  = bx & 7;
    const bool second = (sub >= 4);
    const int bn   = (sub & 3) * 128;

    const __half* Wt  = second ? W2 : W1;
    const float* bias = second ? b2 : b1;
    float* C          = second ? C2 : C1;

    const __half* gsrc[2] = { Ah + (size_t)bm * 512, Wt + (size_t)bn * 512 };

    float acc[4][4][4];
#pragma unroll
    for (int mt = 0; mt < 4; mt++)
#pragma unroll
        for (int nt = 0; nt < 4; nt++)
#pragma unroll
            for (int q = 0; q < 4; q++) acc[mt][nt][q] = 0.f;

    auto load_tile = [&](int buf, int k0) {
#pragma unroll
        for (int i = 0; i < 8; i++) {
            int id  = tid + i * 256;
            int arr = id >> 10;
            int w   = id & 1023;
            int r   = w >> 3;
            int c16 = w & 7;
            __half* s = smem + (buf * 2 + arr) * TILE_E;
            cp16(smem_u32(s + r * ASTR + c16 * 8),
                 gsrc[arr] + (size_t)r * 512 + k0 + c16 * 8);
        }
        asm volatile("cp.async.commit_group;");
    };

    load_tile(0, 0);

    for (int t = 0; t < 8; t++) {
        int buf = t & 1;
        if (t < 7) load_tile(buf ^ 1, (t + 1) * 64);
        if (t < 7) asm volatile("cp.async.wait_group 1;");
        else       asm volatile("cp.async.wait_group 0;");
        __syncthreads();

        const __half* sA = smem + (buf * 2 + 0) * TILE_E;
        const __half* sB = smem + (buf * 2 + 1) * TILE_E;

#pragma unroll
        for (int ks = 0; ks < 4; ks++) {
            unsigned bf[4][2];
#pragma unroll
            for (int nt = 0; nt < 4; nt++) {
                int n = wn * 32 + nt * 8 + (lane & 7);
                int k = ks * 16 + ((lane >> 3) & 1) * 8;
                ldmat_x2(bf[nt], smem_u32(sB + n * ASTR + k));
            }
#pragma unroll
            for (int mt = 0; mt < 4; mt++) {
                int m = wm * 64 + mt * 16 + ((lane >> 3) & 1) * 8 + (lane & 7);
                int k = ks * 16 + ((lane >> 4) & 1) * 8;
                unsigned af[4];
                ldmat_x4(af, smem_u32(sA + m * ASTR + k));
#pragma unroll
                for (int nt = 0; nt < 4; nt++)
                    mma16816h(acc[mt][nt], af, bf[nt]);
            }
        }
        __syncthreads();
    }

    const int g  = lane >> 2;
    const int t4 = lane & 3;
#pragma unroll
    for (int mt = 0; mt < 4; mt++) {
#pragma unroll
        for (int nt = 0; nt < 4; nt++) {
            int row = bm + wm * 64 + mt * 16 + g;
            int col = bn + wn * 32 + nt * 8 + 2 * t4;
            float2 bv = *(const float2*)&bias[col];
            float2 o0 = make_float2(acc[mt][nt][0] + bv.x, acc[mt][nt][1] + bv.y);
            float2 o1 = make_float2(acc[mt][nt][2] + bv.x, acc[mt][nt][3] + bv.y);
            *(float2*)&C[(size_t)row * 512 + col] = o0;
            *(float2*)&C[(size_t)(row + 8) * 512 + col] = o1;
        }
    }
}

// ---------------- L3: fused scatter + dual GEMM ----------------
__global__ void __launch_bounds__(256, 2) scatter_gemm_kernel(
    const int* __restrict__ ei, const __half* __restrict__ Ah,
    const __half* __restrict__ W1, const __half* __restrict__ W2,
    const float* __restrict__ b1, const float* __restrict__ b2,
    float* __restrict__ C1, float* __restrict__ C2)
{
    extern __shared__ __half smem[];
    if (blockIdx.x < 576) {
        int i = blockIdx.x * 256 + threadIdx.x;
        if (i >= ETOT) return;
        int s, d;
        if (i < EDG) { s = ei[i]; d = ei[EDG + i]; }
        else         { s = d = i - EDG; }
        int p = atomicAdd(&g_cur[d], 1);
        g_srcv[p] = s;
        return;
    }
    gemm_body(blockIdx.x - 576, Ah, W1, W2, b1, b2, C1, C2, smem);
}

// standalone dual GEMM (layer 2)
__global__ void __launch_bounds__(256, 2) gemm_dual_kernel(
    const __half* __restrict__ Ah,
    const __half* __restrict__ W1, const __half* __restrict__ W2,
    const float* __restrict__ b1, const float* __restrict__ b2,
    float* __restrict__ C1, float* __restrict__ C2)
{
    extern __shared__ __half smem[];
    gemm_body(blockIdx.x, Ah, W1, W2, b1, b2, C1, C2, smem);
}

// ---------------- small-M GEMM (MLP tail): 4 rows/thread, 256-thread blocks -
__global__ void gemm_small_kernel(
    const float* __restrict__ A, int lda,
    const float* __restrict__ W,
    const float* __restrict__ bias,
    float* __restrict__ C, int M, int Nc, int K)
{
    int n = blockIdx.x * blockDim.x + threadIdx.x;
    int m0 = blockIdx.y * 4;
    if (n >= Nc || m0 >= M) return;
    const float* a0 = A + (size_t)m0 * lda;
    const float* a1 = a0 + lda;
    const float* a2 = a1 + lda;
    const float* a3 = a2 + lda;
    float s0 = 0.f, s1 = 0.f, s2 = 0.f, s3 = 0.f;
    for (int k = 0; k < K; k++) {
        float w = W[(size_t)k * Nc + n];
        s0 += a0[k] * w; s1 += a1[k] * w; s2 += a2[k] * w; s3 += a3[k] * w;
    }
    float bv = bias[n];
    C[(size_t)(m0 + 0) * Nc + n] = s0 + bv;
    C[(size_t)(m0 + 1) * Nc + n] = s1 + bv;
    C[(size_t)(m0 + 2) * Nc + n] = s2 + bv;
    C[(size_t)(m0 + 3) * Nc + n] = s3 + bv;
}

// ---------------- fused GATv2 v3: single stream, branchy online softmax -----
// The post-reduction logit `a` is warp-uniform, so the max-update branch is
// divergence-free. Common path: 1 expf + 1 add + 4 FMA per edge.
__global__ void __launch_bounds__(128) gat_kernel(
    const float* __restrict__ xl, const float* __restrict__ xr,
    const float* __restrict__ att, const float* __restrict__ bias,
    float* __restrict__ out, __half* __restrict__ out16, int mode)
{
    int dst = blockIdx.x;
    int w = threadIdx.x >> 5;
    int l = threadIdx.x & 31;
    int start = g_off[dst];
    int end   = g_off[dst + 1];

    float4 xrr  = ((const float4*)(xr  + (size_t)dst * HC + w * CC))[l];
    float4 attr = ((const float4*)(att + w * CC))[l];

    float mx = -1e30f, den = 0.f;
    float4 acc = make_float4(0.f, 0.f, 0.f, 0.f);

    const float* xb = xl + w * CC;

    for (int c0 = start; c0 < end; c0 += 32) {
        int myi = c0 + l;
        int mysrc = (myi < end) ? g_srcv[myi] : 0;
        int lim = end - c0; if (lim > 32) lim = 32;

        int s0 = __shfl_sync(0xffffffffu, mysrc, 0);
        float4 xv = ((const float4*)(xb + (size_t)s0 * HC))[l];

        for (int jj = 0; jj < lim; jj++) {
            float4 cv = xv;
            if (jj + 1 < lim) {                      // 1-ahead prefetch
                int s = __shfl_sync(0xffffffffu, mysrc, jj + 1);
                xv = ((const float4*)(xb + (size_t)s * HC))[l];
            }
            float v0 = cv.x + xrr.x; v0 = fmaxf(v0, 0.2f * v0);
            float v1 = cv.y + xrr.y; v1 = fmaxf(v1, 0.2f * v1);
            float v2 = cv.z + xrr.z; v2 = fmaxf(v2, 0.2f * v2);
            float v3 = cv.w + xrr.w; v3 = fmaxf(v3, 0.2f * v3);
            float a = v0 * attr.x + v1 * attr.y + v2 * attr.z + v3 * attr.w;
#pragma unroll
            for (int o = 16; o; o >>= 1) a += __shfl_xor_sync(0xffffffffu, a, o);

            if (a <= mx) {                            // warp-uniform, common
                float ew = __expf(a - mx);
                den += ew;
                acc.x += ew * cv.x;
                acc.y += ew * cv.y;
                acc.z += ew * cv.z;
                acc.w += ew * cv.w;
            } else {                                  // rare: new max (ew = 1)
                float sc = __expf(mx - a);            // 0 on first edge
                den = den * sc + 1.0f;
                acc.x = acc.x * sc + cv.x;
                acc.y = acc.y * sc + cv.y;
                acc.z = acc.z * sc + cv.z;
                acc.w = acc.w * sc + cv.w;
                mx = a;
            }
        }
    }

    float inv = 1.0f / (den + 1e-16f);
    float4 bv = ((const float4*)(bias + w * CC))[l];
    float v[4];
    v[0] = acc.x * inv + bv.x;
    v[1] = acc.y * inv + bv.y;
    v[2] = acc.z * inv + bv.z;
    v[3] = acc.w * inv + bv.w;

    if (mode == 0) {
        float g0 = 0.5f * v[0] * (1.0f + erff(v[0] * 0.70710678118654752f));
        float g1 = 0.5f * v[1] * (1.0f + erff(v[1] * 0.70710678118654752f));
        float g2 = 0.5f * v[2] * (1.0f + erff(v[2] * 0.70710678118654752f));
        float g3 = 0.5f * v[3] * (1.0f + erff(v[3] * 0.70710678118654752f));
        __half2 H0 = {__float2half_rn(g0), __float2half_rn(g1)};
        __half2 H1 = {__float2half_rn(g2), __float2half_rn(g3)};
        *(uint2*)(out16 + (size_t)dst * HC + w * CC + 4 * l) =
            make_uint2(*(unsigned*)&H0, *(unsigned*)&H1);
    } else {
        float sq = v[0] * v[0] + v[1] * v[1] + v[2] * v[2] + v[3] * v[3];
#pragma unroll
        for (int o = 16; o; o >>= 1) sq += __shfl_xor_sync(0xffffffffu, sq, o);
        __shared__ float red[4];
        if (l == 0) red[w] = sq;
        __syncthreads();
        float tot = red[0] + red[1] + red[2] + red[3];
        if (threadIdx.x == 0) out[(size_t)dst * D1] = sqrtf(1.0f + tot);
        float* op = out + (size_t)dst * D1 + 1 + w * CC + 4 * l;
        op[0] = v[0]; op[1] = v[1]; op[2] = v[2]; op[3] = v[3];
    }
}

// ---------------- centroid per batch ----------------
__global__ void __launch_bounds__(256) centroid_kernel(
    const float* __restrict__ h3, float* __restrict__ gm)
{
    int b = blockIdx.x;
    __shared__ float avg[D1];
    const float* basep = h3 + (size_t)b * 128 * D1;
    for (int c = threadIdx.x; c < D1; c += blockDim.x) {
        float s = 0.f;
        for (int r = 0; r < 128; r++) s += basep[(size_t)r * D1 + c];
        avg[c] = s * (1.0f / 128.0f);
    }
    __syncthreads();
    float loc = 0.f;
    for (int c = threadIdx.x; c < D1; c += blockDim.x) {
        float a = avg[c];
        loc += (c == 0) ? -a * a : a * a;
    }
#pragma unroll
    for (int o = 16; o; o >>= 1) loc += __shfl_xor_sync(0xffffffffu, loc, o);
    __shared__ float red[8];
    int w = threadIdx.x >> 5, l = threadIdx.x & 31;
    if (l == 0) red[w] = loc;
    __syncthreads();
    __shared__ float s_invden;
    if (threadIdx.x == 0) {
        float inner = 0.f;
        for (int i = 0; i < 8; i++) inner += red[i];
        s_invden = 1.0f / sqrtf(fmaxf(-inner, 1e-8f));
    }
    __syncthreads();
    float invd = s_invden;
    for (int c = threadIdx.x; c < D1; c += blockDim.x)
        gm[(size_t)b * D1 + c] = avg[c] * invd;
}

// ---------------- llin epilogue (standalone) ----------------
__global__ void __launch_bounds__(256) llin_post_kernel(
    const float* __restrict__ zin, float* __restrict__ zout,
    const float* __restrict__ sptr, int D)
{
    int b = blockIdx.x;
    const float* row = zin + (size_t)b * D;
    float loc = 0.f;
    for (int c = 1 + threadIdx.x; c < D; c += blockDim.x) { float v = row[c]; loc += v * v; }
#pragma unroll
    for (int o = 16; o; o >>= 1) loc += __shfl_xor_sync(0xffffffffu, loc, o);
    __shared__ float red[8];
    int w = threadIdx.x >> 5, l = threadIdx.x & 31;
    if (l == 0) red[w] = loc;
    __syncthreads();
    __shared__ float s_t, s_scale;
    if (threadIdx.x == 0) {
        float sq = 0.f;
        for (int i = 0; i < 8; i++) sq += red[i];
        sq = fmaxf(sq, 1e-8f);
        float z0 = row[0];
        float t = (1.0f / (1.0f + expf(-z0))) * expf(*sptr) + 1.1f;
        s_t = t;
        s_scale = sqrtf((t * t - 1.0f) / sq);
    }
    __syncthreads();
    if (threadIdx.x == 0) zout[(size_t)b * D] = s_t;
    float sc = s_scale;
    for (int c = 1 + threadIdx.x; c < D; c += blockDim.x)
        zout[(size_t)b * D + c] = row[c] * sc;
}

// ---------------- fused llin + gelu + add_time (za -> z2) ----------------
__global__ void __launch_bounds__(256) llin_gelu_kernel(
    const float* __restrict__ za, float* __restrict__ z2,
    const float* __restrict__ sptr, int D)
{
    int b = blockIdx.x;
    const float* row = za + (size_t)b * D;
    float* orow = z2 + (size_t)b * D;
    int w = threadIdx.x >> 5, l = threadIdx.x & 31;
    __shared__ float red[8];

    float loc = 0.f;
    for (int c = 1 + threadIdx.x; c < D; c += blockDim.x) { float v = row[c]; loc += v * v; }
#pragma unroll
    for (int o = 16; o; o >>= 1) loc += __shfl_xor_sync(0xffffffffu, loc, o);
    if (l == 0) red[w] = loc;
    __syncthreads();
    __shared__ float s_scale;
    if (threadIdx.x == 0) {
        float sq = 0.f;
        for (int i = 0; i < 8; i++) sq += red[i];
        sq = fmaxf(sq, 1e-8f);
        float z0 = row[0];
        float t = (1.0f / (1.0f + expf(-z0))) * expf(*sptr) + 1.1f;
        s_scale = sqrtf((t * t - 1.0f) / sq);
    }
    __syncthreads();
    float sc = s_scale;

    float loc2 = 0.f;
    for (int c = 1 + threadIdx.x; c < D; c += blockDim.x) {
        float z1 = row[c] * sc;
        float g = 0.5f * z1 * (1.0f + erff(z1 * 0.70710678118654752f));
        orow[c] = g;
        loc2 += g * g;
    }
#pragma unroll
    for (int o = 16; o; o >>= 1) loc2 += __shfl_xor_sync(0xffffffffu, loc2, o);
    __syncthreads();
    if (l == 0) red[w] = loc2;
    __syncthreads();
    if (threadIdx.x == 0) {
        float tot = 0.f;
        for (int i = 0; i < 8; i++) tot += red[i];
        orow[0] = sqrtf(1.0f + tot);
    }
}

// ---------------- launch ----------------
extern "C" void kernel_launch(void* const* d_in, const int* in_sizes, int n_in,
                              void* d_out, int out_size)
{
    const float* x  = (const float*)d_in[0];
    const int*   ei = (const int*)d_in[1];
    int base = 2;
    if (n_in > 2 && in_sizes[2] == 1) base = 3;

    const float* Wl1   = (const float*)d_in[base + 0];
    const float* bl1   = (const float*)d_in[base + 1];
    const float* Wr1   = (const float*)d_in[base + 2];
    const float* br1   = (const float*)d_in[base + 3];
    const float* att1  = (const float*)d_in[base + 4];
    const float* bias1 = (const float*)d_in[base + 5];
    const float* Wl2   = (const float*)d_in[base + 6];
    const float* bl2   = (const float*)d_in[base + 7];
    const float* Wr2   = (const float*)d_in[base + 8];
    const float* br2   = (const float*)d_in[base + 9];
    const float* att2  = (const float*)d_in[base + 10];
    const float* bias2 = (const float*)d_in[base + 11];
    const float* Wa    = (const float*)d_in[base + 12];
    const float* ba    = (const float*)d_in[base + 13];
    const float* sa    = (const float*)d_in[base + 14];
    const float* Wb    = (const float*)d_in[base + 15];
    const float* bb    = (const float*)d_in[base + 16];
    const float* sb    = (const float*)d_in[base + 17];
    const float* Wf    = (const float*)d_in[base + 18];
    const float* bf    = (const float*)d_in[base + 19];
    const float* sf    = (const float*)d_in[base + 20];

    float* out = (float*)d_out;

    void* p;
    cudaGetSymbolAddress(&p, g_xl); float* pxl = (float*)p;
    cudaGetSymbolAddress(&p, g_xr); float* pxr = (float*)p;
    cudaGetSymbolAddress(&p, g_h3); float* ph3 = (float*)p;
    cudaGetSymbolAddress(&p, g_za); float* pza = (float*)p;
    cudaGetSymbolAddress(&p, g_z2); float* pz2 = (float*)p;
    cudaGetSymbolAddress(&p, g_zb); float* pzb = (float*)p;
    cudaGetSymbolAddress(&p, g_z3); float* pz3 = (float*)p;
    cudaGetSymbolAddress(&p, g_zf); float* pzf = (float*)p;
    cudaGetSymbolAddress(&p, g_A16); __half* pA  = (__half*)p;
    cudaGetSymbolAddress(&p, g_W1t); __half* pW1 = (__half*)p;
    cudaGetSymbolAddress(&p, g_W2t); __half* pW2 = (__half*)p;
    cudaGetSymbolAddress(&p, g_W3t); __half* pW3 = (__half*)p;
    cudaGetSymbolAddress(&p, g_W4t); __half* pW4 = (__half*)p;

    static bool attr_set = false;
    if (!attr_set) {
        cudaFuncSetAttribute(gemm_dual_kernel,
                             cudaFuncAttributeMaxDynamicSharedMemorySize, GEMM_SMEM);
        cudaFuncSetAttribute(scatter_gemm_kernel,
                             cudaFuncAttributeMaxDynamicSharedMemorySize, GEMM_SMEM);
        attr_set = true;
    }

    // L1: convA + splitWT(Wl1,Wr1,Wl2,Wr2) + hist   (9216 + 576 = 9792 blocks)
    prep_kernel<<<9792, 256>>>(x, ei, Wl1, Wr1, Wl2, Wr2, pA);
    // L2: scan (also re-zeros deg)
    scan_kernel<<<1, 1024>>>();
    // L3: scatter + layer-1 dual GEMM
    scatter_gemm_kernel<<<576 + 1024, 256, GEMM_SMEM>>>(ei, pA, pW1, pW2, bl1, br1, pxl, pxr);
    // L4: layer-1 GAT
    gat_kernel<<<NV, 128>>>(pxl, pxr, att1, bias1, nullptr, pA, 0);

    // layer 2 (W3/W4 already transposed by prep)
    gemm_dual_kernel<<<dim3(8 * 128), 256, GEMM_SMEM>>>(pA, pW3, pW4, bl2, br2, pxl, pxr);
    gat_kernel<<<NV, 128>>>(pxl, pxr, att2, bias2, ph3, nullptr, 1);

    // centroid -> second half of output
    centroid_kernel<<<BB, 256>>>(ph3, out + (size_t)BB * D1);

    // MLP head
    gemm_small_kernel<<<dim3((DA + 255) / 256, BB / 4), 256>>>(ph3, 128 * D1, Wa, ba, pza, BB, DA, D1);
    llin_gelu_kernel<<<BB, 256>>>(pza, pz2, sa, DA);
    gemm_small_kernel<<<dim3((D1 + 255) / 256, BB / 4), 256>>>(pz2, DA, Wb, bb, pzb, BB, D1, DA);
    llin_post_kernel<<<BB, 256>>>(pzb, pz3, sb, D1);
    gemm_small_kernel<<<dim3((D1 + 255) / 256, BB / 4), 256>>>(pz3, D1, Wf, bf, pzf, BB, D1, D1);
    llin_post_kernel<<<BB, 256>>>(pzf, out, sf, D1);

    (void)out_size;
}